// round 1
// baseline (speedup 1.0000x reference)
#include <cuda_runtime.h>
#include <math.h>

// Problem constants
static constexpr int kT = 512;
static constexpr int kB = 16;
static constexpr int kD = 2048;

// Scratch (device globals: no allocation allowed)
__device__ float g_Xp[kT * kB * kD];     // X @ Wx, [T*B, D]
__device__ float g_H [kT * kB * kD];     // all hidden states, [T*B, D]
__device__ float g_part[4 * kB * kD];    // split-K partials, [4][B][D]
__device__ unsigned g_count = 0;
__device__ unsigned g_sense = 0;

// ---------------------------------------------------------------------------
// Classic fp32 SGEMM: C[M,N] = A[M,K] @ B[K,N], row-major, dims divisible by tile
// 128x128 block tile, BK=8, 256 threads, 8x8 per-thread microtile.
// ---------------------------------------------------------------------------
__global__ __launch_bounds__(256) void sgemm_kernel(
    const float* __restrict__ A, const float* __restrict__ B,
    float* __restrict__ C, int M, int N, int K)
{
    constexpr int BM = 128, BN = 128, BK = 8, TM = 8, TN = 8;
    __shared__ float As[BK][BM];
    __shared__ float Bs[BK][BN];

    const int tid = threadIdx.x;
    const int crow0 = blockIdx.y * BM;
    const int ccol0 = blockIdx.x * BN;

    const float* Ab = A + (size_t)crow0 * K;
    const float* Bp = B + ccol0;

    const int aRow = tid >> 1;            // 0..127
    const int aCol = (tid & 1) * 4;       // 0 or 4
    const int bRow = tid >> 5;            // 0..7
    const int bCol = (tid & 31) * 4;      // 0..124
    const int tr = (tid >> 4) * TM;       // 0..120
    const int tc = (tid & 15) * TN;       // 0..120

    float acc[TM][TN];
    #pragma unroll
    for (int i = 0; i < TM; i++)
        #pragma unroll
        for (int j = 0; j < TN; j++) acc[i][j] = 0.0f;

    for (int k0 = 0; k0 < K; k0 += BK) {
        float4 a4 = *reinterpret_cast<const float4*>(Ab + (size_t)aRow * K + k0 + aCol);
        As[aCol + 0][aRow] = a4.x;
        As[aCol + 1][aRow] = a4.y;
        As[aCol + 2][aRow] = a4.z;
        As[aCol + 3][aRow] = a4.w;
        *reinterpret_cast<float4*>(&Bs[bRow][bCol]) =
            *reinterpret_cast<const float4*>(Bp + (size_t)(k0 + bRow) * N + bCol);
        __syncthreads();

        #pragma unroll
        for (int kk = 0; kk < BK; kk++) {
            float ra[TM], rb[TN];
            #pragma unroll
            for (int i = 0; i < TM; i++) ra[i] = As[kk][tr + i];
            #pragma unroll
            for (int j = 0; j < TN; j++) rb[j] = Bs[kk][tc + j];
            #pragma unroll
            for (int i = 0; i < TM; i++)
                #pragma unroll
                for (int j = 0; j < TN; j++)
                    acc[i][j] += ra[i] * rb[j];
        }
        __syncthreads();
    }

    float* Cp = C + (size_t)crow0 * N + ccol0;
    #pragma unroll
    for (int i = 0; i < TM; i++)
        #pragma unroll
        for (int j = 0; j < TN; j += 4) {
            float4 v = make_float4(acc[i][j], acc[i][j+1], acc[i][j+2], acc[i][j+3]);
            *reinterpret_cast<float4*>(Cp + (size_t)(tr + i) * N + tc + j) = v;
        }
}

// ---------------------------------------------------------------------------
// Persistent recurrence kernel. 128 CTAs x 256 threads (all co-resident on
// 148 SMs). Per step:
//   phase 1: split-K partial GEMM h_prev @ Wh  (ksplit=4, d-tile=64)
//   barrier
//   phase 2: reduce partials + Xp, tanh -> g_H[t]
//   barrier
// ---------------------------------------------------------------------------
__device__ __forceinline__ void grid_barrier() {
    __syncthreads();
    if (threadIdx.x == 0) {
        __threadfence();
        unsigned gen = *((volatile unsigned*)&g_sense);
        if (atomicAdd(&g_count, 1) == gridDim.x - 1) {
            *((volatile unsigned*)&g_count) = 0;
            __threadfence();
            atomicAdd(&g_sense, 1);
        } else {
            while (*((volatile unsigned*)&g_sense) == gen) { __nanosleep(64); }
        }
        __threadfence();
    }
    __syncthreads();
}

__global__ __launch_bounds__(256) void rnn_scan_kernel(
    const float* __restrict__ h0, const float* __restrict__ Wh,
    float* __restrict__ hfinal_out)
{
    constexpr int KS = 512;       // K range per block (ksplit = 4)
    constexpr int DT = 64;        // d columns per block (32 d-tiles)
    constexpr int HSTRIDE = KS + 4; // pad to avoid smem bank conflict (516)
    __shared__ float hs[kB * HSTRIDE];   // staged h slice [16][512], ~33KB

    const int tid = threadIdx.x;
    const int blk = blockIdx.x;
    const int dtile = (blk & 31) * DT;
    const int kseg  = (blk >> 5);          // 0..3
    const int ks    = kseg * KS;
    const int b = tid >> 4;                // 0..15
    const int d = dtile + (tid & 15) * 4;  // float4 of output columns

    for (int t = 0; t < kT; t++) {
        const float* hprev = (t == 0) ? h0 : (g_H + (size_t)(t - 1) * kB * kD);

        // stage h_prev[0:16][ks:ks+512] into shared memory (bypass L1: these
        // addresses were written by other SMs earlier in this same launch)
        {
            const int nf4 = kB * KS / 4;   // 2048 float4 loads
            for (int i = tid; i < nf4; i += 256) {
                int row = i >> 7;          // / (KS/4)
                int c4  = i & 127;
                float4 v = __ldcg(reinterpret_cast<const float4*>(
                               hprev + (size_t)row * kD + ks) + c4);
                *reinterpret_cast<float4*>(hs + row * HSTRIDE + (c4 << 2)) = v;
            }
            __syncthreads();
        }

        // phase 1: partial acc[d..d+3] over k in [ks, ks+KS)
        float4 acc = make_float4(0.f, 0.f, 0.f, 0.f);
        const float* wp = Wh + (size_t)ks * kD + d;
        const float* hrow = hs + b * HSTRIDE;
        #pragma unroll 8
        for (int k = 0; k < KS; k++) {
            float hv = hrow[k];
            float4 w = __ldg(reinterpret_cast<const float4*>(wp));
            acc.x += hv * w.x;
            acc.y += hv * w.y;
            acc.z += hv * w.z;
            acc.w += hv * w.w;
            wp += kD;
        }
        *reinterpret_cast<float4*>(g_part + ((size_t)kseg * kB + b) * kD + d) = acc;

        grid_barrier();

        // phase 2: reduce 4 partials + Xp, tanh, store h_t
        {
            int idx = blk * 256 + tid;     // 0..32767 == B*D
            int bb = idx >> 11;            // /2048
            int dd = idx & 2047;
            size_t off = (size_t)bb * kD + dd;
            float s = __ldg(g_Xp + (size_t)t * kB * kD + off);
            s += __ldcg(g_part + off);
            s += __ldcg(g_part + (size_t)1 * kB * kD + off);
            s += __ldcg(g_part + (size_t)2 * kB * kD + off);
            s += __ldcg(g_part + (size_t)3 * kB * kD + off);
            float h = tanhf(s);
            g_H[(size_t)t * kB * kD + off] = h;
            if (t == kT - 1) hfinal_out[off] = h;
        }

        grid_barrier();
    }
}

// ---------------------------------------------------------------------------
// Launch: Xp = X@Wx  ->  persistent scan  ->  Y = H@Wo
// Output layout: [h_final (B*D) | ys (T*B*D)]
// ---------------------------------------------------------------------------
extern "C" void kernel_launch(void* const* d_in, const int* in_sizes, int n_in,
                              void* d_out, int out_size)
{
    const float* h0 = (const float*)d_in[0];
    const float* x  = (const float*)d_in[1];
    const float* Wx = (const float*)d_in[2];
    const float* Wh = (const float*)d_in[3];
    const float* Wo = (const float*)d_in[4];

    float* out  = (float*)d_out;
    float* hfin = out;                 // [B, D]
    float* ys   = out + kB * kD;       // [T, B, D]

    float* Xp = nullptr;
    float* H  = nullptr;
    cudaGetSymbolAddress((void**)&Xp, g_Xp);
    cudaGetSymbolAddress((void**)&H,  g_H);

    dim3 gemm_grid(kD / 128, (kT * kB) / 128);  // (16, 64)

    // 1) Xp = X @ Wx   (X viewed as [T*B, D])
    sgemm_kernel<<<gemm_grid, 256>>>(x, Wx, Xp, kT * kB, kD, kD);

    // 2) sequential scan: g_H[t] = tanh(Xp[t] + h_{t-1} @ Wh); writes h_final
    rnn_scan_kernel<<<128, 256>>>(h0, Wh, hfin);

    // 3) ys = H @ Wo
    sgemm_kernel<<<gemm_grid, 256>>>(H, Wo, ys, kT * kB, kD, kD);
}

// round 2
// speedup vs baseline: 1.8838x; 1.8838x over previous
#include <cuda_runtime.h>
#include <math.h>

static constexpr int kT = 512;
static constexpr int kB = 16;
static constexpr int kD = 2048;
static constexpr int kBD = kB * kD;          // 32768

// Scratch (device globals; no allocation allowed)
__device__ float g_Xp[kT * kBD];             // X @ Wx   [T*B, D]
__device__ float g_H [kT * kBD];             // hidden states [T*B, D]
__device__ unsigned g_count = 0;
__device__ unsigned g_sense = 0;

// ---------------------------------------------------------------------------
// SGEMM v2: C[M,N] = A[M,K] @ B[K,N]; 128x128 tile, BK=8, 256 thr, 8x8 micro,
// double-buffered smem (1 syncthreads per k-tile), 4+4 split fragments
// (conflict-free LDS.128).
// ---------------------------------------------------------------------------
__global__ __launch_bounds__(256, 2) void sgemm2_kernel(
    const float* __restrict__ A, const float* __restrict__ B,
    float* __restrict__ C, int M, int N, int K)
{
    constexpr int BM = 128, BN = 128, BK = 8;
    __shared__ float As[2][BK][BM];
    __shared__ float Bs[2][BK][BN];

    const int tid = threadIdx.x;
    const int crow0 = blockIdx.y * BM;
    const int ccol0 = blockIdx.x * BN;

    const float* Ab = A + (size_t)crow0 * K;
    const float* Bp = B + ccol0;

    const int aRow = tid >> 1;             // 0..127
    const int aCol = (tid & 1) * 4;        // 0 or 4
    const int bRow = tid >> 5;             // 0..7
    const int bCol = (tid & 31) * 4;       // 0..124
    const int tr4 = (tid >> 4) * 4;        // 0..60
    const int tc4 = (tid & 15) * 4;        // 0..60

    float acc[8][8];
    #pragma unroll
    for (int i = 0; i < 8; i++)
        #pragma unroll
        for (int j = 0; j < 8; j++) acc[i][j] = 0.0f;

    // preload tile 0 into buffer 0
    float4 a4 = *reinterpret_cast<const float4*>(Ab + (size_t)aRow * K + aCol);
    float4 b4 = *reinterpret_cast<const float4*>(Bp + (size_t)bRow * N + bCol);
    As[0][aCol + 0][aRow] = a4.x;
    As[0][aCol + 1][aRow] = a4.y;
    As[0][aCol + 2][aRow] = a4.z;
    As[0][aCol + 3][aRow] = a4.w;
    *reinterpret_cast<float4*>(&Bs[0][bRow][bCol]) = b4;
    __syncthreads();

    const int nTiles = K / BK;
    for (int tile = 0; tile < nTiles; tile++) {
        const int cur = tile & 1;
        const bool hasNext = (tile + 1 < nTiles);
        if (hasNext) {
            const int k0 = (tile + 1) * BK;
            a4 = *reinterpret_cast<const float4*>(Ab + (size_t)aRow * K + k0 + aCol);
            b4 = *reinterpret_cast<const float4*>(Bp + (size_t)(k0 + bRow) * N + bCol);
        }

        #pragma unroll
        for (int kk = 0; kk < BK; kk++) {
            float4 ra0 = *reinterpret_cast<const float4*>(&As[cur][kk][tr4]);
            float4 ra1 = *reinterpret_cast<const float4*>(&As[cur][kk][tr4 + 64]);
            float4 rb0 = *reinterpret_cast<const float4*>(&Bs[cur][kk][tc4]);
            float4 rb1 = *reinterpret_cast<const float4*>(&Bs[cur][kk][tc4 + 64]);
            float ra[8] = {ra0.x, ra0.y, ra0.z, ra0.w, ra1.x, ra1.y, ra1.z, ra1.w};
            float rb[8] = {rb0.x, rb0.y, rb0.z, rb0.w, rb1.x, rb1.y, rb1.z, rb1.w};
            #pragma unroll
            for (int i = 0; i < 8; i++)
                #pragma unroll
                for (int j = 0; j < 8; j++)
                    acc[i][j] += ra[i] * rb[j];
        }

        if (hasNext) {
            const int nxt = cur ^ 1;
            As[nxt][aCol + 0][aRow] = a4.x;
            As[nxt][aCol + 1][aRow] = a4.y;
            As[nxt][aCol + 2][aRow] = a4.z;
            As[nxt][aCol + 3][aRow] = a4.w;
            *reinterpret_cast<float4*>(&Bs[nxt][bRow][bCol]) = b4;
            __syncthreads();
        }
    }

    float* Cp = C + (size_t)crow0 * N + ccol0;
    #pragma unroll
    for (int half = 0; half < 2; half++) {
        #pragma unroll
        for (int i = 0; i < 4; i++) {
            const int r = half * 64 + tr4 + i;
            const int ai = half * 4 + i;
            float4 v0 = make_float4(acc[ai][0], acc[ai][1], acc[ai][2], acc[ai][3]);
            float4 v1 = make_float4(acc[ai][4], acc[ai][5], acc[ai][6], acc[ai][7]);
            *reinterpret_cast<float4*>(Cp + (size_t)r * N + tc4) = v0;
            *reinterpret_cast<float4*>(Cp + (size_t)r * N + tc4 + 64) = v1;
        }
    }
}

// ---------------------------------------------------------------------------
// Persistent recurrence. 128 CTAs x 256 threads, 1 CTA/SM (132KB smem).
// Each CTA owns 16 output columns (dtile). Wh slice [2048 x 16] lives in smem
// for the whole kernel. Split-K is block-local: 4 k-segments across warps,
// reduced via smem. ONE grid barrier per step.
// ---------------------------------------------------------------------------
__device__ __forceinline__ void grid_barrier() {
    __syncthreads();
    if (threadIdx.x == 0) {
        __threadfence();
        unsigned gen = *((volatile unsigned*)&g_sense);
        if (atomicAdd(&g_count, 1) == gridDim.x - 1) {
            *((volatile unsigned*)&g_count) = 0;
            __threadfence();
            atomicAdd(&g_sense, 1);
        } else {
            while (*((volatile unsigned*)&g_sense) == gen) { }
        }
        __threadfence();
    }
    __syncthreads();
}

__global__ __launch_bounds__(256, 1) void rnn_scan_kernel(
    const float* __restrict__ h0, const float* __restrict__ Wh,
    float* __restrict__ hfinal_out)
{
    constexpr int DT = 16;                  // output columns per block
    extern __shared__ float smem[];
    float* whs  = smem;                     // [2048][16]  (128 KB)
    float* part = smem + kD * DT;           // [4][16][16] (4 KB)

    const int tid   = threadIdx.x;
    const int blk   = blockIdx.x;
    const int dtile = blk * DT;

    const int kseg = tid >> 6;              // 0..3   (warp-pair per kseg)
    const int b    = (tid >> 2) & 15;       // 0..15
    const int d4   = tid & 3;               // 0..3   (float4 within 16 cols)
    const int ks   = kseg * 512;

    // Load this block's Wh slice into smem once (reused for all 512 steps).
    for (int i = tid; i < kD * 4; i += 256) {      // 8192 float4
        int k = i >> 2, j4 = i & 3;
        float4 v = *reinterpret_cast<const float4*>(Wh + (size_t)k * kD + dtile + j4 * 4);
        *reinterpret_cast<float4*>(whs + k * DT + j4 * 4) = v;
    }
    __syncthreads();

    const float* wbase = whs + (size_t)ks * DT + d4 * 4;
    const int b2 = tid >> 4;                // reduce-phase mapping
    const int dd = tid & 15;

    for (int t = 0; t < kT; t++) {
        const float* hp = (t == 0) ? h0 : (g_H + (size_t)(t - 1) * kBD);
        const float* hrow = hp + (size_t)b * kD + ks;

        float4 acc = make_float4(0.f, 0.f, 0.f, 0.f);
        #pragma unroll 1
        for (int k = 0; k < 512; k += 16) {
            float4 hv0 = __ldcg(reinterpret_cast<const float4*>(hrow + k));
            float4 hv1 = __ldcg(reinterpret_cast<const float4*>(hrow + k + 4));
            float4 hv2 = __ldcg(reinterpret_cast<const float4*>(hrow + k + 8));
            float4 hv3 = __ldcg(reinterpret_cast<const float4*>(hrow + k + 12));
            const float hvals[16] = {hv0.x, hv0.y, hv0.z, hv0.w,
                                     hv1.x, hv1.y, hv1.z, hv1.w,
                                     hv2.x, hv2.y, hv2.z, hv2.w,
                                     hv3.x, hv3.y, hv3.z, hv3.w};
            #pragma unroll
            for (int c = 0; c < 16; c++) {
                float h = hvals[c];
                float4 w = *reinterpret_cast<const float4*>(wbase + (size_t)(k + c) * DT);
                acc.x += h * w.x;
                acc.y += h * w.y;
                acc.z += h * w.z;
                acc.w += h * w.w;
            }
        }
        *reinterpret_cast<float4*>(part + kseg * 256 + b * DT + d4 * 4) = acc;
        __syncthreads();

        // block-local reduce + bias(Xp) + tanh -> h_t (one element per thread)
        {
            size_t off = (size_t)b2 * kD + dtile + dd;
            float s = __ldg(g_Xp + (size_t)t * kBD + off);
            int p = b2 * DT + dd;
            s += part[p] + part[256 + p] + part[512 + p] + part[768 + p];
            float h = tanhf(s);
            g_H[(size_t)t * kBD + off] = h;
            if (t == kT - 1) hfinal_out[off] = h;
        }

        grid_barrier();
    }
}

// ---------------------------------------------------------------------------
// Launch: Xp = X@Wx  ->  persistent scan  ->  Y = H@Wo
// Output layout: [h_final (B*D) | ys (T*B*D)]
// ---------------------------------------------------------------------------
extern "C" void kernel_launch(void* const* d_in, const int* in_sizes, int n_in,
                              void* d_out, int out_size)
{
    const float* h0 = (const float*)d_in[0];
    const float* x  = (const float*)d_in[1];
    const float* Wx = (const float*)d_in[2];
    const float* Wh = (const float*)d_in[3];
    const float* Wo = (const float*)d_in[4];

    float* out  = (float*)d_out;
    float* hfin = out;                 // [B, D]
    float* ys   = out + kBD;           // [T, B, D]

    float* Xp = nullptr;
    float* H  = nullptr;
    cudaGetSymbolAddress((void**)&Xp, g_Xp);
    cudaGetSymbolAddress((void**)&H,  g_H);

    const int scan_smem = (kD * 16 + 4 * 16 * 16) * sizeof(float);  // 132 KB
    cudaFuncSetAttribute(rnn_scan_kernel,
                         cudaFuncAttributeMaxDynamicSharedMemorySize, scan_smem);

    dim3 gemm_grid(kD / 128, (kT * kB) / 128);  // (16, 64)

    // 1) Xp = X @ Wx   (X viewed as [T*B, D])
    sgemm2_kernel<<<gemm_grid, 256>>>(x, Wx, Xp, kT * kB, kD, kD);

    // 2) sequential scan: g_H[t] = tanh(Xp[t] + h_{t-1} @ Wh); writes h_final
    rnn_scan_kernel<<<128, 256, scan_smem>>>(h0, Wh, hfin);

    // 3) ys = H @ Wo
    sgemm2_kernel<<<gemm_grid, 256>>>(H, Wo, ys, kT * kB, kD, kD);
}

// round 4
// speedup vs baseline: 2.1894x; 1.1622x over previous
#include <cuda_runtime.h>
#include <cuda_bf16.h>
#include <math.h>
#include <stdint.h>

static constexpr int kT = 512;
static constexpr int kB = 16;
static constexpr int kD = 2048;
static constexpr int kBD = kB * kD;          // 32768
static constexpr int kM = kT * kB;           // 8192 rows in big GEMMs

// Scratch (device globals; no allocation allowed)
__device__ float g_Xp[kT * kBD];                 // X @ Wx   [T*B, D]
__device__ float g_H [kT * kBD];                 // hidden states fp32
__device__ __nv_bfloat16 g_A0[kM * kD];          // bf16 hi split of GEMM A operand
__device__ __nv_bfloat16 g_A1[kM * kD];          // bf16 lo split
__device__ __nv_bfloat16 g_WxT0[kD * kD];        // Wx^T split hi  [N][K]
__device__ __nv_bfloat16 g_WxT1[kD * kD];
__device__ __nv_bfloat16 g_WoT0[kD * kD];
__device__ __nv_bfloat16 g_WoT1[kD * kD];
__device__ unsigned g_count = 0;
__device__ unsigned g_sense = 0;

// ===========================================================================
// PTX helpers — base sm_103 ISA only (NO tcgen05/'a' features: ptxas targets
// sm_103 without the arch-accelerated feature set).
// ===========================================================================
__device__ __forceinline__ uint32_t smem_u32(const void* p) {
    uint32_t a;
    asm("{ .reg .u64 t; cvta.to.shared.u64 t, %1; cvt.u32.u64 %0, t; }"
        : "=r"(a) : "l"(p));
    return a;
}
#define CP_ASYNC16(dst, src) \
    asm volatile("cp.async.cg.shared.global [%0], [%1], 16;" \
                 :: "r"(dst), "l"(src) : "memory")
#define CP_COMMIT() asm volatile("cp.async.commit_group;" ::: "memory")
#define CP_WAIT1()  asm volatile("cp.async.wait_group 1;" ::: "memory")

#define LDMATRIX_X4(r, addr) \
    asm volatile("ldmatrix.sync.aligned.m8n8.x4.shared.b16 {%0,%1,%2,%3}, [%4];" \
        : "=r"((r)[0]), "=r"((r)[1]), "=r"((r)[2]), "=r"((r)[3]) : "r"(addr))

#define MMA16816(d, a, b0, b1) \
    asm volatile("mma.sync.aligned.m16n8k16.row.col.f32.bf16.bf16.f32 " \
        "{%0,%1,%2,%3}, {%4,%5,%6,%7}, {%8,%9}, {%0,%1,%2,%3};" \
        : "+f"((d)[0]), "+f"((d)[1]), "+f"((d)[2]), "+f"((d)[3]) \
        : "r"((a)[0]), "r"((a)[1]), "r"((a)[2]), "r"((a)[3]), "r"(b0), "r"(b1))

#define SMEM_SWIZZLE_128B(x) ((x) ^ (((x) >> 3) & 0x70))

__device__ __forceinline__ unsigned pack_bf2(__nv_bfloat16 a, __nv_bfloat16 b) {
    __nv_bfloat162 h = __halves2bfloat162(a, b);
    return *reinterpret_cast<unsigned*>(&h);
}

// ===========================================================================
// Prep: W [K,N] fp32 -> W^T split into bf16 hi/lo, [N][K]
// ===========================================================================
__global__ void prep_wT_kernel(const float* __restrict__ W,
                               __nv_bfloat16* __restrict__ T0,
                               __nv_bfloat16* __restrict__ T1)
{
    __shared__ float tile[32][33];
    const int n0 = blockIdx.x * 32, k0 = blockIdx.y * 32;
    const int tx = threadIdx.x, ty = threadIdx.y;
    tile[ty][tx] = W[(size_t)(k0 + ty) * kD + n0 + tx];
    __syncthreads();
    float v = tile[tx][ty];                       // = W[k0+tx][n0+ty]
    __nv_bfloat16 b0 = __float2bfloat16_rn(v);
    float r = v - __bfloat162float(b0);
    __nv_bfloat16 b1 = __float2bfloat16_rn(r);
    size_t o = (size_t)(n0 + ty) * kD + k0 + tx;  // T[n][k]
    T0[o] = b0;
    T1[o] = b1;
}

// fp32 -> bf16 hi/lo splits (elementwise, float4 granularity)
__global__ void split_bf16_kernel(const float* __restrict__ in,
                                  __nv_bfloat16* __restrict__ o0,
                                  __nv_bfloat16* __restrict__ o1, int n4)
{
    int i = blockIdx.x * blockDim.x + threadIdx.x;
    if (i >= n4) return;
    float4 v = __ldg(reinterpret_cast<const float4*>(in) + i);
    __nv_bfloat16 hx = __float2bfloat16_rn(v.x);
    __nv_bfloat16 hy = __float2bfloat16_rn(v.y);
    __nv_bfloat16 hz = __float2bfloat16_rn(v.z);
    __nv_bfloat16 hw = __float2bfloat16_rn(v.w);
    __nv_bfloat16 lx = __float2bfloat16_rn(v.x - __bfloat162float(hx));
    __nv_bfloat16 ly = __float2bfloat16_rn(v.y - __bfloat162float(hy));
    __nv_bfloat16 lz = __float2bfloat16_rn(v.z - __bfloat162float(hz));
    __nv_bfloat16 lw = __float2bfloat16_rn(v.w - __bfloat162float(hw));
    uint2 p0 = make_uint2(pack_bf2(hx, hy), pack_bf2(hz, hw));
    uint2 p1 = make_uint2(pack_bf2(lx, ly), pack_bf2(lz, lw));
    reinterpret_cast<uint2*>(o0)[i] = p0;
    reinterpret_cast<uint2*>(o1)[i] = p1;
}

// ===========================================================================
// HMMA bf16x3 GEMM: C[kM,kD] = A(split hi/lo [M][K]) @ B(split hi/lo [N][K])^T
// 128x128 CTA tile, BK=64, 8 warps (32x64 warp tiles), cp.async double buffer.
// Accumulates a0b0 + a0b1 + a1b0 in fp32.
// ===========================================================================
__global__ __launch_bounds__(256, 1) void gemm_bf16_kernel(
    const __nv_bfloat16* __restrict__ A0, const __nv_bfloat16* __restrict__ A1,
    const __nv_bfloat16* __restrict__ B0, const __nv_bfloat16* __restrict__ B1,
    float* __restrict__ C)
{
    extern __shared__ char sm[];   // [2 bufs][4 tiles][16384B]; tile=[128][64] bf16 SW128

    const int tid = threadIdx.x;
    const int wid = tid >> 5;
    const int lane = tid & 31;
    const int m0 = blockIdx.y * 128, n0 = blockIdx.x * 128;
    const int wm = (wid & 3) * 32;       // warp row offset
    const int wn = (wid >> 2) * 64;      // warp col offset

    auto stage = [&](int buf, int c) {
        const int k0 = c * 64;
        char* base = sm + buf * 65536;
        const __nv_bfloat16* srcs[4] = {
            A0 + (size_t)m0 * kD + k0, A1 + (size_t)m0 * kD + k0,
            B0 + (size_t)n0 * kD + k0, B1 + (size_t)n0 * kD + k0 };
        #pragma unroll
        for (int tile = 0; tile < 4; tile++) {
            #pragma unroll
            for (int j = 0; j < 4; j++) {
                int lin = tid + j * 256;        // 0..1023
                int row = lin >> 3, c16 = lin & 7;
                const __nv_bfloat16* src = srcs[tile] + (size_t)row * kD + c16 * 8;
                uint32_t dst = smem_u32(base + tile * 16384 +
                                        SMEM_SWIZZLE_128B(row * 128 + c16 * 16));
                CP_ASYNC16(dst, src);
            }
        }
        CP_COMMIT();
    };

    float acc[2][8][4];
    #pragma unroll
    for (int i = 0; i < 2; i++)
        #pragma unroll
        for (int j = 0; j < 8; j++)
            #pragma unroll
            for (int q = 0; q < 4; q++) acc[i][j][q] = 0.0f;

    stage(0, 0);
    stage(1, 1);

    for (int c = 0; c < 32; c++) {
        CP_WAIT1();
        __syncthreads();
        const uint32_t base = smem_u32(sm + (c & 1) * 65536);
        const uint32_t a0b = base, a1b = base + 16384;
        const uint32_t b0b = base + 32768, b1b = base + 49152;

        #pragma unroll
        for (int kk = 0; kk < 4; kk++) {
            uint32_t a0f[2][4], a1f[2][4];
            #pragma unroll
            for (int mt = 0; mt < 2; mt++) {
                int row = wm + mt * 16 + (lane & 15);
                uint32_t off = SMEM_SWIZZLE_128B(row * 128 + kk * 32 + (lane >> 4) * 16);
                LDMATRIX_X4(a0f[mt], a0b + off);
                LDMATRIX_X4(a1f[mt], a1b + off);
            }
            #pragma unroll
            for (int p = 0; p < 4; p++) {
                int nrow = wn + p * 16 + (lane & 15);
                uint32_t boff = SMEM_SWIZZLE_128B(nrow * 128 + kk * 32 + (lane >> 4) * 16);
                uint32_t f0[4], f1[4];
                LDMATRIX_X4(f0, b0b + boff);
                LDMATRIX_X4(f1, b1b + boff);
                #pragma unroll
                for (int mt = 0; mt < 2; mt++) {
                    MMA16816(acc[mt][2 * p],     a0f[mt], f0[0], f0[2]);
                    MMA16816(acc[mt][2 * p + 1], a0f[mt], f0[1], f0[3]);
                    MMA16816(acc[mt][2 * p],     a0f[mt], f1[0], f1[2]);
                    MMA16816(acc[mt][2 * p + 1], a0f[mt], f1[1], f1[3]);
                    MMA16816(acc[mt][2 * p],     a1f[mt], f0[0], f0[2]);
                    MMA16816(acc[mt][2 * p + 1], a1f[mt], f0[1], f0[3]);
                }
            }
        }
        __syncthreads();
        if (c + 2 < 32) stage(c & 1, c + 2);
    }

    // Epilogue: per-warp register tiles -> C (fp32)
    #pragma unroll
    for (int mt = 0; mt < 2; mt++) {
        #pragma unroll
        for (int nt = 0; nt < 8; nt++) {
            int r = m0 + wm + mt * 16 + (lane >> 2);
            int col = n0 + wn + nt * 8 + (lane & 3) * 2;
            float2 v0 = make_float2(acc[mt][nt][0], acc[mt][nt][1]);
            float2 v1 = make_float2(acc[mt][nt][2], acc[mt][nt][3]);
            *reinterpret_cast<float2*>(C + (size_t)r * kD + col) = v0;
            *reinterpret_cast<float2*>(C + (size_t)(r + 8) * kD + col) = v1;
        }
    }
}

// ===========================================================================
// Persistent recurrence (R2 design; now also emits bf16 splits of h for the
// downstream tensor-core GEMM)
// ===========================================================================
__device__ __forceinline__ void grid_barrier() {
    __syncthreads();
    if (threadIdx.x == 0) {
        __threadfence();
        unsigned gen = *((volatile unsigned*)&g_sense);
        if (atomicAdd(&g_count, 1) == gridDim.x - 1) {
            *((volatile unsigned*)&g_count) = 0;
            __threadfence();
            atomicAdd(&g_sense, 1);
        } else {
            while (*((volatile unsigned*)&g_sense) == gen) { }
        }
        __threadfence();
    }
    __syncthreads();
}

__global__ __launch_bounds__(256, 1) void rnn_scan_kernel(
    const float* __restrict__ h0, const float* __restrict__ Wh,
    float* __restrict__ hfinal_out)
{
    constexpr int DT = 16;
    extern __shared__ float smem[];
    float* whs  = smem;                     // [2048][16] (128 KB)
    float* part = smem + kD * DT;           // [4][16][16]

    const int tid   = threadIdx.x;
    const int blk   = blockIdx.x;
    const int dtile = blk * DT;

    const int kseg = tid >> 6;
    const int b    = (tid >> 2) & 15;
    const int d4   = tid & 3;
    const int ks   = kseg * 512;

    for (int i = tid; i < kD * 4; i += 256) {
        int k = i >> 2, j4 = i & 3;
        float4 v = *reinterpret_cast<const float4*>(Wh + (size_t)k * kD + dtile + j4 * 4);
        *reinterpret_cast<float4*>(whs + k * DT + j4 * 4) = v;
    }
    __syncthreads();

    const float* wbase = whs + (size_t)ks * DT + d4 * 4;
    const int b2 = tid >> 4;
    const int dd = tid & 15;

    for (int t = 0; t < kT; t++) {
        const float* hp = (t == 0) ? h0 : (g_H + (size_t)(t - 1) * kBD);
        const float* hrow = hp + (size_t)b * kD + ks;

        float4 acc = make_float4(0.f, 0.f, 0.f, 0.f);
        #pragma unroll 1
        for (int k = 0; k < 512; k += 16) {
            float4 hv0 = __ldcg(reinterpret_cast<const float4*>(hrow + k));
            float4 hv1 = __ldcg(reinterpret_cast<const float4*>(hrow + k + 4));
            float4 hv2 = __ldcg(reinterpret_cast<const float4*>(hrow + k + 8));
            float4 hv3 = __ldcg(reinterpret_cast<const float4*>(hrow + k + 12));
            const float hvals[16] = {hv0.x, hv0.y, hv0.z, hv0.w,
                                     hv1.x, hv1.y, hv1.z, hv1.w,
                                     hv2.x, hv2.y, hv2.z, hv2.w,
                                     hv3.x, hv3.y, hv3.z, hv3.w};
            #pragma unroll
            for (int cc = 0; cc < 16; cc++) {
                float h = hvals[cc];
                float4 w = *reinterpret_cast<const float4*>(wbase + (size_t)(k + cc) * DT);
                acc.x += h * w.x;
                acc.y += h * w.y;
                acc.z += h * w.z;
                acc.w += h * w.w;
            }
        }
        *reinterpret_cast<float4*>(part + kseg * 256 + b * DT + d4 * 4) = acc;
        __syncthreads();

        {
            size_t off = (size_t)b2 * kD + dtile + dd;
            float s = __ldg(g_Xp + (size_t)t * kBD + off);
            int p = b2 * DT + dd;
            s += part[p] + part[256 + p] + part[512 + p] + part[768 + p];
            float h = tanhf(s);
            size_t go = (size_t)t * kBD + off;
            g_H[go] = h;
            __nv_bfloat16 hb = __float2bfloat16_rn(h);
            g_A0[go] = hb;
            g_A1[go] = __float2bfloat16_rn(h - __bfloat162float(hb));
            if (t == kT - 1) hfinal_out[off] = h;
        }

        grid_barrier();
    }
}

// ===========================================================================
// Launch
// ===========================================================================
extern "C" void kernel_launch(void* const* d_in, const int* in_sizes, int n_in,
                              void* d_out, int out_size)
{
    const float* h0 = (const float*)d_in[0];
    const float* x  = (const float*)d_in[1];
    const float* Wx = (const float*)d_in[2];
    const float* Wh = (const float*)d_in[3];
    const float* Wo = (const float*)d_in[4];

    float* out  = (float*)d_out;
    float* hfin = out;                 // [B, D]
    float* ys   = out + kBD;           // [T, B, D]

    float *Xp, *H;
    __nv_bfloat16 *A0, *A1, *WxT0, *WxT1, *WoT0, *WoT1;
    cudaGetSymbolAddress((void**)&Xp,   g_Xp);
    cudaGetSymbolAddress((void**)&H,    g_H);
    cudaGetSymbolAddress((void**)&A0,   g_A0);
    cudaGetSymbolAddress((void**)&A1,   g_A1);
    cudaGetSymbolAddress((void**)&WxT0, g_WxT0);
    cudaGetSymbolAddress((void**)&WxT1, g_WxT1);
    cudaGetSymbolAddress((void**)&WoT0, g_WoT0);
    cudaGetSymbolAddress((void**)&WoT1, g_WoT1);

    const int gemm_smem = 2 * 65536;                                // 128 KB
    const int scan_smem = (kD * 16 + 4 * 16 * 16) * sizeof(float);  // 132 KB
    cudaFuncSetAttribute(gemm_bf16_kernel,
                         cudaFuncAttributeMaxDynamicSharedMemorySize, gemm_smem);
    cudaFuncSetAttribute(rnn_scan_kernel,
                         cudaFuncAttributeMaxDynamicSharedMemorySize, scan_smem);

    dim3 prep_grid(kD / 32, kD / 32), prep_blk(32, 32);
    prep_wT_kernel<<<prep_grid, prep_blk>>>(Wx, WxT0, WxT1);
    prep_wT_kernel<<<prep_grid, prep_blk>>>(Wo, WoT0, WoT1);

    const int n4 = kM * kD / 4;
    split_bf16_kernel<<<(n4 + 255) / 256, 256>>>(x, A0, A1, n4);

    dim3 gemm_grid(kD / 128, kM / 128);   // (16, 64)

    // 1) Xp = X @ Wx  (HMMA bf16x3)
    gemm_bf16_kernel<<<gemm_grid, 256, gemm_smem>>>(A0, A1, WxT0, WxT1, Xp);

    // 2) sequential scan (also writes bf16 splits of H into A0/A1)
    rnn_scan_kernel<<<128, 256, scan_smem>>>(h0, Wh, hfin);

    // 3) ys = H @ Wo  (HMMA bf16x3)
    gemm_bf16_kernel<<<gemm_grid, 256, gemm_smem>>>(A0, A1, WoT0, WoT1, ys);
}

// round 5
// speedup vs baseline: 5.5541x; 2.5368x over previous
#include <cuda_runtime.h>
#include <cuda_bf16.h>
#include <math.h>
#include <stdint.h>

static constexpr int kT = 512;
static constexpr int kB = 16;
static constexpr int kD = 2048;
static constexpr int kBD = kB * kD;          // 32768
static constexpr int kM = kT * kB;           // 8192 rows in big GEMMs

// Scratch (device globals; no allocation allowed)
__device__ float g_Xp[kT * kBD];                 // X @ Wx   [T*B, D]
__device__ __nv_bfloat16 g_Hs0[(kT + 1) * kBD]; // h bf16 hi; slot t = h_{t-1}
__device__ __nv_bfloat16 g_Hs1[(kT + 1) * kBD]; // h bf16 lo
__device__ __nv_bfloat16 g_Xs0[kM * kD];         // x bf16 hi
__device__ __nv_bfloat16 g_Xs1[kM * kD];         // x bf16 lo
__device__ __nv_bfloat16 g_WxT0[kD * kD];        // W^T splits, [N][K]
__device__ __nv_bfloat16 g_WxT1[kD * kD];
__device__ __nv_bfloat16 g_WoT0[kD * kD];
__device__ __nv_bfloat16 g_WoT1[kD * kD];
__device__ __nv_bfloat16 g_WhT0[kD * kD];
__device__ __nv_bfloat16 g_WhT1[kD * kD];
__device__ unsigned g_count = 0;
__device__ unsigned g_sense = 0;

// ===========================================================================
// PTX helpers — base sm_103 ISA only (no 'a'-gated features)
// ===========================================================================
__device__ __forceinline__ uint32_t smem_u32(const void* p) {
    uint32_t a;
    asm("{ .reg .u64 t; cvta.to.shared.u64 t, %1; cvt.u32.u64 %0, t; }"
        : "=r"(a) : "l"(p));
    return a;
}
#define CP_ASYNC16(dst, src) \
    asm volatile("cp.async.cg.shared.global [%0], [%1], 16;" \
                 :: "r"(dst), "l"(src) : "memory")
#define CP_COMMIT() asm volatile("cp.async.commit_group;" ::: "memory")
#define CP_WAIT1()  asm volatile("cp.async.wait_group 1;" ::: "memory")
#define CP_WAIT0()  asm volatile("cp.async.wait_group 0;" ::: "memory")

#define LDMATRIX_X4(r, addr) \
    asm volatile("ldmatrix.sync.aligned.m8n8.x4.shared.b16 {%0,%1,%2,%3}, [%4];" \
        : "=r"((r)[0]), "=r"((r)[1]), "=r"((r)[2]), "=r"((r)[3]) : "r"(addr))

#define MMA16816(d, a, b0, b1) \
    asm volatile("mma.sync.aligned.m16n8k16.row.col.f32.bf16.bf16.f32 " \
        "{%0,%1,%2,%3}, {%4,%5,%6,%7}, {%8,%9}, {%0,%1,%2,%3};" \
        : "+f"((d)[0]), "+f"((d)[1]), "+f"((d)[2]), "+f"((d)[3]) \
        : "r"((a)[0]), "r"((a)[1]), "r"((a)[2]), "r"((a)[3]), "r"(b0), "r"(b1))

#define SMEM_SWIZZLE_128B(x) ((x) ^ (((x) >> 3) & 0x70))

__device__ __forceinline__ unsigned pack_bf2(__nv_bfloat16 a, __nv_bfloat16 b) {
    __nv_bfloat162 h = __halves2bfloat162(a, b);
    return *reinterpret_cast<unsigned*>(&h);
}

// ===========================================================================
// Prep: W [K,N] fp32 -> W^T split into bf16 hi/lo, [N][K]
// ===========================================================================
__global__ void prep_wT_kernel(const float* __restrict__ W,
                               __nv_bfloat16* __restrict__ T0,
                               __nv_bfloat16* __restrict__ T1)
{
    __shared__ float tile[32][33];
    const int n0 = blockIdx.x * 32, k0 = blockIdx.y * 32;
    const int tx = threadIdx.x, ty = threadIdx.y;
    tile[ty][tx] = W[(size_t)(k0 + ty) * kD + n0 + tx];
    __syncthreads();
    float v = tile[tx][ty];                       // = W[k0+tx][n0+ty]
    __nv_bfloat16 b0 = __float2bfloat16_rn(v);
    float r = v - __bfloat162float(b0);
    __nv_bfloat16 b1 = __float2bfloat16_rn(r);
    size_t o = (size_t)(n0 + ty) * kD + k0 + tx;  // T[n][k]
    T0[o] = b0;
    T1[o] = b1;
}

// fp32 -> bf16 hi/lo splits (elementwise, float4 granularity)
__global__ void split_bf16_kernel(const float* __restrict__ in,
                                  __nv_bfloat16* __restrict__ o0,
                                  __nv_bfloat16* __restrict__ o1, int n4)
{
    int i = blockIdx.x * blockDim.x + threadIdx.x;
    if (i >= n4) return;
    float4 v = __ldg(reinterpret_cast<const float4*>(in) + i);
    __nv_bfloat16 hx = __float2bfloat16_rn(v.x);
    __nv_bfloat16 hy = __float2bfloat16_rn(v.y);
    __nv_bfloat16 hz = __float2bfloat16_rn(v.z);
    __nv_bfloat16 hw = __float2bfloat16_rn(v.w);
    __nv_bfloat16 lx = __float2bfloat16_rn(v.x - __bfloat162float(hx));
    __nv_bfloat16 ly = __float2bfloat16_rn(v.y - __bfloat162float(hy));
    __nv_bfloat16 lz = __float2bfloat16_rn(v.z - __bfloat162float(hz));
    __nv_bfloat16 lw = __float2bfloat16_rn(v.w - __bfloat162float(hw));
    uint2 p0 = make_uint2(pack_bf2(hx, hy), pack_bf2(hz, hw));
    uint2 p1 = make_uint2(pack_bf2(lx, ly), pack_bf2(lz, lw));
    reinterpret_cast<uint2*>(o0)[i] = p0;
    reinterpret_cast<uint2*>(o1)[i] = p1;
}

// ===========================================================================
// HMMA bf16x3 GEMM (unchanged from R4): C = A(split [M][K]) @ B(split [N][K])^T
// ===========================================================================
__global__ __launch_bounds__(256, 1) void gemm_bf16_kernel(
    const __nv_bfloat16* __restrict__ A0, const __nv_bfloat16* __restrict__ A1,
    const __nv_bfloat16* __restrict__ B0, const __nv_bfloat16* __restrict__ B1,
    float* __restrict__ C)
{
    extern __shared__ char sm[];   // [2 bufs][4 tiles][16384B]

    const int tid = threadIdx.x;
    const int wid = tid >> 5;
    const int lane = tid & 31;
    const int m0 = blockIdx.y * 128, n0 = blockIdx.x * 128;
    const int wm = (wid & 3) * 32;
    const int wn = (wid >> 2) * 64;

    auto stage = [&](int buf, int c) {
        const int k0 = c * 64;
        char* base = sm + buf * 65536;
        const __nv_bfloat16* srcs[4] = {
            A0 + (size_t)m0 * kD + k0, A1 + (size_t)m0 * kD + k0,
            B0 + (size_t)n0 * kD + k0, B1 + (size_t)n0 * kD + k0 };
        #pragma unroll
        for (int tile = 0; tile < 4; tile++) {
            #pragma unroll
            for (int j = 0; j < 4; j++) {
                int lin = tid + j * 256;
                int row = lin >> 3, c16 = lin & 7;
                const __nv_bfloat16* src = srcs[tile] + (size_t)row * kD + c16 * 8;
                uint32_t dst = smem_u32(base + tile * 16384 +
                                        SMEM_SWIZZLE_128B(row * 128 + c16 * 16));
                CP_ASYNC16(dst, src);
            }
        }
        CP_COMMIT();
    };

    float acc[2][8][4];
    #pragma unroll
    for (int i = 0; i < 2; i++)
        #pragma unroll
        for (int j = 0; j < 8; j++)
            #pragma unroll
            for (int q = 0; q < 4; q++) acc[i][j][q] = 0.0f;

    stage(0, 0);
    stage(1, 1);

    for (int c = 0; c < 32; c++) {
        CP_WAIT1();
        __syncthreads();
        const uint32_t base = smem_u32(sm + (c & 1) * 65536);
        const uint32_t a0b = base, a1b = base + 16384;
        const uint32_t b0b = base + 32768, b1b = base + 49152;

        #pragma unroll
        for (int kk = 0; kk < 4; kk++) {
            uint32_t a0f[2][4], a1f[2][4];
            #pragma unroll
            for (int mt = 0; mt < 2; mt++) {
                int row = wm + mt * 16 + (lane & 15);
                uint32_t off = SMEM_SWIZZLE_128B(row * 128 + kk * 32 + (lane >> 4) * 16);
                LDMATRIX_X4(a0f[mt], a0b + off);
                LDMATRIX_X4(a1f[mt], a1b + off);
            }
            #pragma unroll
            for (int p = 0; p < 4; p++) {
                int nrow = wn + p * 16 + (lane & 15);
                uint32_t boff = SMEM_SWIZZLE_128B(nrow * 128 + kk * 32 + (lane >> 4) * 16);
                uint32_t f0[4], f1[4];
                LDMATRIX_X4(f0, b0b + boff);
                LDMATRIX_X4(f1, b1b + boff);
                #pragma unroll
                for (int mt = 0; mt < 2; mt++) {
                    MMA16816(acc[mt][2 * p],     a0f[mt], f0[0], f0[2]);
                    MMA16816(acc[mt][2 * p + 1], a0f[mt], f0[1], f0[3]);
                    MMA16816(acc[mt][2 * p],     a0f[mt], f1[0], f1[2]);
                    MMA16816(acc[mt][2 * p + 1], a0f[mt], f1[1], f1[3]);
                    MMA16816(acc[mt][2 * p],     a1f[mt], f0[0], f0[2]);
                    MMA16816(acc[mt][2 * p + 1], a1f[mt], f0[1], f0[3]);
                }
            }
        }
        __syncthreads();
        if (c + 2 < 32) stage(c & 1, c + 2);
    }

    #pragma unroll
    for (int mt = 0; mt < 2; mt++) {
        #pragma unroll
        for (int nt = 0; nt < 8; nt++) {
            int r = m0 + wm + mt * 16 + (lane >> 2);
            int col = n0 + wn + nt * 8 + (lane & 3) * 2;
            float2 v0 = make_float2(acc[mt][nt][0], acc[mt][nt][1]);
            float2 v1 = make_float2(acc[mt][nt][2], acc[mt][nt][3]);
            *reinterpret_cast<float2*>(C + (size_t)r * kD + col) = v0;
            *reinterpret_cast<float2*>(C + (size_t)(r + 8) * kD + col) = v1;
        }
    }
}

// ===========================================================================
// Persistent tensor-core recurrence. 128 CTAs x 256 thr. CTA owns 16 output
// cols, full K=2048. Wh fragments live in REGISTERS (loaded once). One grid
// barrier per step. h stored as bf16 hi/lo (consumed by Y GEMM).
// ===========================================================================
__device__ __forceinline__ void grid_barrier() {
    __syncthreads();
    if (threadIdx.x == 0) {
        __threadfence();
        unsigned gen = *((volatile unsigned*)&g_sense);
        if (atomicAdd(&g_count, 1) == gridDim.x - 1) {
            *((volatile unsigned*)&g_count) = 0;
            __threadfence();
            atomicAdd(&g_sense, 1);
        } else {
            while (*((volatile unsigned*)&g_sense) == gen) { }
        }
        __threadfence();
    }
    __syncthreads();
}

__global__ __launch_bounds__(256, 1) void rnn_scan_mma_kernel(
    const __nv_bfloat16* __restrict__ WhT0,
    const __nv_bfloat16* __restrict__ WhT1,
    float* __restrict__ hfinal_out)
{
    // dyn smem: [0,64K) h-hi chunks [32][16][64]; [64K,128K) h-lo; [128K,+8K) partials
    extern __shared__ char dsm_raw[];
    const uint32_t raw = smem_u32(dsm_raw);
    const uint32_t base = (raw + 1023u) & ~1023u;
    char* dsm = dsm_raw + (base - raw);
    float* part = reinterpret_cast<float*>(dsm + 131072);

    const int tid = threadIdx.x;
    const int wid = tid >> 5;
    const int lane = tid & 31;
    const int n0 = blockIdx.x * 16;

    // ---- init: stage Wh^T slice [n0:n0+16][0:2048] hi/lo, extract B frags ----
    {
        const __nv_bfloat16* s0 = WhT0 + (size_t)n0 * kD;
        const __nv_bfloat16* s1 = WhT1 + (size_t)n0 * kD;
        for (int i = tid; i < 4096; i += 256) {
            int row = i >> 8, u = i & 255, ch = u >> 3, c8 = u & 7;
            size_t so = (size_t)row * kD + ch * 64 + c8 * 8;
            uint32_t doff = ch * 2048 + SMEM_SWIZZLE_128B(row * 128 + c8 * 16);
            CP_ASYNC16(base + doff, s0 + so);
            CP_ASYNC16(base + 65536 + doff, s1 + so);
        }
        CP_COMMIT();
        CP_WAIT0();
        __syncthreads();
    }

    uint32_t bh[16][4], bl[16][4];       // 128 regs of resident Wh fragments
    #pragma unroll
    for (int s = 0; s < 16; s++) {
        const int ch = wid * 4 + (s >> 2), kk = s & 3;
        const uint32_t off = ch * 2048 +
            SMEM_SWIZZLE_128B((lane & 15) * 128 + kk * 32 + (lane >> 4) * 16);
        LDMATRIX_X4(bh[s], base + off);
        LDMATRIX_X4(bl[s], base + 65536 + off);
    }
    __syncthreads();   // Wh smem region now reused for h staging

    const int r0 = lane >> 2;
    const int cb = (lane & 3) * 2;
    const int rrow = tid >> 4;            // reduce-phase mapping
    const int rcol = tid & 15;

    for (int t = 0; t < kT; t++) {
        // stage h_{t-1} (bf16 hi/lo) -> smem chunks
        const __nv_bfloat16* h0p = g_Hs0 + (size_t)t * kBD;
        const __nv_bfloat16* h1p = g_Hs1 + (size_t)t * kBD;
        for (int i = tid; i < 4096; i += 256) {
            int row = i >> 8, u = i & 255, ch = u >> 3, c8 = u & 7;
            size_t so = (size_t)row * kD + ch * 64 + c8 * 8;
            uint32_t doff = ch * 2048 + SMEM_SWIZZLE_128B(row * 128 + c8 * 16);
            CP_ASYNC16(base + doff, h0p + so);
            CP_ASYNC16(base + 65536 + doff, h1p + so);
        }
        CP_COMMIT();
        CP_WAIT0();
        __syncthreads();

        float acc[2][4];
        #pragma unroll
        for (int p = 0; p < 2; p++)
            #pragma unroll
            for (int q = 0; q < 4; q++) acc[p][q] = 0.0f;

        #pragma unroll
        for (int s = 0; s < 16; s++) {
            const int ch = wid * 4 + (s >> 2), kk = s & 3;
            const uint32_t off = ch * 2048 +
                SMEM_SWIZZLE_128B((lane & 15) * 128 + kk * 32 + (lane >> 4) * 16);
            uint32_t a0[4], a1[4];
            LDMATRIX_X4(a0, base + off);
            LDMATRIX_X4(a1, base + 65536 + off);
            MMA16816(acc[0], a0, bh[s][0], bh[s][2]);
            MMA16816(acc[1], a0, bh[s][1], bh[s][3]);
            MMA16816(acc[0], a0, bl[s][0], bl[s][2]);
            MMA16816(acc[1], a0, bl[s][1], bl[s][3]);
            MMA16816(acc[0], a1, bh[s][0], bh[s][2]);
            MMA16816(acc[1], a1, bh[s][1], bh[s][3]);
        }

        // per-warp partials -> smem
        #pragma unroll
        for (int p = 0; p < 2; p++) {
            *reinterpret_cast<float2*>(&part[wid * 256 + r0 * 16 + p * 8 + cb]) =
                make_float2(acc[p][0], acc[p][1]);
            *reinterpret_cast<float2*>(&part[wid * 256 + (r0 + 8) * 16 + p * 8 + cb]) =
                make_float2(acc[p][2], acc[p][3]);
        }
        __syncthreads();

        // reduce 8 warps + Xp, tanh, split, store
        {
            float s = g_Xp[(size_t)t * kBD + (size_t)rrow * kD + n0 + rcol];
            #pragma unroll
            for (int w = 0; w < 8; w++) s += part[w * 256 + tid];
            float h = tanhf(s);
            __nv_bfloat16 hb = __float2bfloat16_rn(h);
            size_t go = (size_t)(t + 1) * kBD + (size_t)rrow * kD + n0 + rcol;
            g_Hs0[go] = hb;
            g_Hs1[go] = __float2bfloat16_rn(h - __bfloat162float(hb));
            if (t == kT - 1)
                hfinal_out[(size_t)rrow * kD + n0 + rcol] = h;
        }

        grid_barrier();
    }
}

// ===========================================================================
// Launch
// ===========================================================================
extern "C" void kernel_launch(void* const* d_in, const int* in_sizes, int n_in,
                              void* d_out, int out_size)
{
    const float* h0 = (const float*)d_in[0];
    const float* x  = (const float*)d_in[1];
    const float* Wx = (const float*)d_in[2];
    const float* Wh = (const float*)d_in[3];
    const float* Wo = (const float*)d_in[4];

    float* out  = (float*)d_out;
    float* hfin = out;                 // [B, D]
    float* ys   = out + kBD;           // [T, B, D]

    float* Xp;
    __nv_bfloat16 *Hs0, *Hs1, *Xs0, *Xs1, *WxT0, *WxT1, *WoT0, *WoT1, *WhT0, *WhT1;
    cudaGetSymbolAddress((void**)&Xp,   g_Xp);
    cudaGetSymbolAddress((void**)&Hs0,  g_Hs0);
    cudaGetSymbolAddress((void**)&Hs1,  g_Hs1);
    cudaGetSymbolAddress((void**)&Xs0,  g_Xs0);
    cudaGetSymbolAddress((void**)&Xs1,  g_Xs1);
    cudaGetSymbolAddress((void**)&WxT0, g_WxT0);
    cudaGetSymbolAddress((void**)&WxT1, g_WxT1);
    cudaGetSymbolAddress((void**)&WoT0, g_WoT0);
    cudaGetSymbolAddress((void**)&WoT1, g_WoT1);
    cudaGetSymbolAddress((void**)&WhT0, g_WhT0);
    cudaGetSymbolAddress((void**)&WhT1, g_WhT1);

    const int gemm_smem = 2 * 65536;                 // 128 KB
    const int scan_smem = 131072 + 8192 + 1024;      // 140 KB (h hi/lo + partials + align)
    cudaFuncSetAttribute(gemm_bf16_kernel,
                         cudaFuncAttributeMaxDynamicSharedMemorySize, gemm_smem);
    cudaFuncSetAttribute(rnn_scan_mma_kernel,
                         cudaFuncAttributeMaxDynamicSharedMemorySize, scan_smem);

    dim3 prep_grid(kD / 32, kD / 32), prep_blk(32, 32);
    prep_wT_kernel<<<prep_grid, prep_blk>>>(Wx, WxT0, WxT1);
    prep_wT_kernel<<<prep_grid, prep_blk>>>(Wo, WoT0, WoT1);
    prep_wT_kernel<<<prep_grid, prep_blk>>>(Wh, WhT0, WhT1);

    const int n4x = kM * kD / 4;
    split_bf16_kernel<<<(n4x + 255) / 256, 256>>>(x, Xs0, Xs1, n4x);
    const int n4h = kBD / 4;
    split_bf16_kernel<<<(n4h + 255) / 256, 256>>>(h0, Hs0, Hs1, n4h);  // slot 0

    dim3 gemm_grid(kD / 128, kM / 128);   // (16, 64)

    // 1) Xp = X @ Wx  (HMMA bf16x3)
    gemm_bf16_kernel<<<gemm_grid, 256, gemm_smem>>>(Xs0, Xs1, WxT0, WxT1, Xp);

    // 2) sequential scan: tensor-core recurrence, writes Hs slots 1..T
    rnn_scan_mma_kernel<<<128, 256, scan_smem>>>(WhT0, WhT1, hfin);

    // 3) ys = H @ Wo  (HMMA bf16x3; A = Hs slots 1..T)
    gemm_bf16_kernel<<<gemm_grid, 256, gemm_smem>>>(Hs0 + kBD, Hs1 + kBD,
                                                    WoT0, WoT1, ys);
}

// round 6
// speedup vs baseline: 5.9309x; 1.0678x over previous
#include <cuda_runtime.h>
#include <cuda_bf16.h>
#include <math.h>
#include <stdint.h>

static constexpr int kT = 512;
static constexpr int kB = 16;
static constexpr int kD = 2048;
static constexpr int kBD = kB * kD;          // 32768
static constexpr int kM = kT * kB;           // 8192 rows in big GEMMs

// Scratch (device globals; no allocation allowed)
__device__ float g_Xp[kT * kBD];                 // X @ Wx   [T*B, D]
__device__ __nv_bfloat16 g_Hs0[(kT + 1) * kBD]; // h bf16 hi; slot t = h_{t-1}
__device__ __nv_bfloat16 g_Hs1[(kT + 1) * kBD]; // h bf16 lo
__device__ __nv_bfloat16 g_Xs0[kM * kD];         // x bf16 hi
__device__ __nv_bfloat16 g_Xs1[kM * kD];         // x bf16 lo
__device__ __nv_bfloat16 g_WxT0[kD * kD];        // W^T splits, [N][K]
__device__ __nv_bfloat16 g_WxT1[kD * kD];
__device__ __nv_bfloat16 g_WoT0[kD * kD];
__device__ __nv_bfloat16 g_WoT1[kD * kD];
__device__ __nv_bfloat16 g_WhT0[kD * kD];
__device__ __nv_bfloat16 g_WhT1[kD * kD];
__device__ unsigned g_count = 0;
__device__ unsigned g_sense = 0;

// ===========================================================================
// PTX helpers — base sm_103 ISA only (no 'a'-gated features)
// ===========================================================================
__device__ __forceinline__ uint32_t smem_u32(const void* p) {
    uint32_t a;
    asm("{ .reg .u64 t; cvta.to.shared.u64 t, %1; cvt.u32.u64 %0, t; }"
        : "=r"(a) : "l"(p));
    return a;
}
#define CP_ASYNC16(dst, src) \
    asm volatile("cp.async.cg.shared.global [%0], [%1], 16;" \
                 :: "r"(dst), "l"(src) : "memory")
#define CP_COMMIT() asm volatile("cp.async.commit_group;" ::: "memory")
#define CP_WAIT1()  asm volatile("cp.async.wait_group 1;" ::: "memory")
#define CP_WAIT0()  asm volatile("cp.async.wait_group 0;" ::: "memory")

#define LDMATRIX_X4(r, addr) \
    asm volatile("ldmatrix.sync.aligned.m8n8.x4.shared.b16 {%0,%1,%2,%3}, [%4];" \
        : "=r"((r)[0]), "=r"((r)[1]), "=r"((r)[2]), "=r"((r)[3]) : "r"(addr))

#define MMA16816(d, a, b0, b1) \
    asm volatile("mma.sync.aligned.m16n8k16.row.col.f32.bf16.bf16.f32 " \
        "{%0,%1,%2,%3}, {%4,%5,%6,%7}, {%8,%9}, {%0,%1,%2,%3};" \
        : "+f"((d)[0]), "+f"((d)[1]), "+f"((d)[2]), "+f"((d)[3]) \
        : "r"((a)[0]), "r"((a)[1]), "r"((a)[2]), "r"((a)[3]), "r"(b0), "r"(b1))

#define SMEM_SWIZZLE_128B(x) ((x) ^ (((x) >> 3) & 0x70))

__device__ __forceinline__ unsigned pack_bf2(__nv_bfloat16 a, __nv_bfloat16 b) {
    __nv_bfloat162 h = __halves2bfloat162(a, b);
    return *reinterpret_cast<unsigned*>(&h);
}

// ===========================================================================
// Prep: W [K,N] fp32 -> W^T split into bf16 hi/lo, [N][K]
// ===========================================================================
__global__ void prep_wT_kernel(const float* __restrict__ W,
                               __nv_bfloat16* __restrict__ T0,
                               __nv_bfloat16* __restrict__ T1)
{
    __shared__ float tile[32][33];
    const int n0 = blockIdx.x * 32, k0 = blockIdx.y * 32;
    const int tx = threadIdx.x, ty = threadIdx.y;
    tile[ty][tx] = W[(size_t)(k0 + ty) * kD + n0 + tx];
    __syncthreads();
    float v = tile[tx][ty];                       // = W[k0+tx][n0+ty]
    __nv_bfloat16 b0 = __float2bfloat16_rn(v);
    float r = v - __bfloat162float(b0);
    __nv_bfloat16 b1 = __float2bfloat16_rn(r);
    size_t o = (size_t)(n0 + ty) * kD + k0 + tx;  // T[n][k]
    T0[o] = b0;
    T1[o] = b1;
}

// fp32 -> bf16 hi/lo splits (elementwise, float4 granularity)
__global__ void split_bf16_kernel(const float* __restrict__ in,
                                  __nv_bfloat16* __restrict__ o0,
                                  __nv_bfloat16* __restrict__ o1, int n4)
{
    int i = blockIdx.x * blockDim.x + threadIdx.x;
    if (i >= n4) return;
    float4 v = __ldg(reinterpret_cast<const float4*>(in) + i);
    __nv_bfloat16 hx = __float2bfloat16_rn(v.x);
    __nv_bfloat16 hy = __float2bfloat16_rn(v.y);
    __nv_bfloat16 hz = __float2bfloat16_rn(v.z);
    __nv_bfloat16 hw = __float2bfloat16_rn(v.w);
    __nv_bfloat16 lx = __float2bfloat16_rn(v.x - __bfloat162float(hx));
    __nv_bfloat16 ly = __float2bfloat16_rn(v.y - __bfloat162float(hy));
    __nv_bfloat16 lz = __float2bfloat16_rn(v.z - __bfloat162float(hz));
    __nv_bfloat16 lw = __float2bfloat16_rn(v.w - __bfloat162float(hw));
    uint2 p0 = make_uint2(pack_bf2(hx, hy), pack_bf2(hz, hw));
    uint2 p1 = make_uint2(pack_bf2(lx, ly), pack_bf2(lz, lw));
    reinterpret_cast<uint2*>(o0)[i] = p0;
    reinterpret_cast<uint2*>(o1)[i] = p1;
}

// ===========================================================================
// HMMA bf16x3 GEMM (unchanged): C = A(split [M][K]) @ B(split [N][K])^T
// ===========================================================================
__global__ __launch_bounds__(256, 1) void gemm_bf16_kernel(
    const __nv_bfloat16* __restrict__ A0, const __nv_bfloat16* __restrict__ A1,
    const __nv_bfloat16* __restrict__ B0, const __nv_bfloat16* __restrict__ B1,
    float* __restrict__ C)
{
    extern __shared__ char sm[];   // [2 bufs][4 tiles][16384B]

    const int tid = threadIdx.x;
    const int wid = tid >> 5;
    const int lane = tid & 31;
    const int m0 = blockIdx.y * 128, n0 = blockIdx.x * 128;
    const int wm = (wid & 3) * 32;
    const int wn = (wid >> 2) * 64;

    auto stage = [&](int buf, int c) {
        const int k0 = c * 64;
        char* base = sm + buf * 65536;
        const __nv_bfloat16* srcs[4] = {
            A0 + (size_t)m0 * kD + k0, A1 + (size_t)m0 * kD + k0,
            B0 + (size_t)n0 * kD + k0, B1 + (size_t)n0 * kD + k0 };
        #pragma unroll
        for (int tile = 0; tile < 4; tile++) {
            #pragma unroll
            for (int j = 0; j < 4; j++) {
                int lin = tid + j * 256;
                int row = lin >> 3, c16 = lin & 7;
                const __nv_bfloat16* src = srcs[tile] + (size_t)row * kD + c16 * 8;
                uint32_t dst = smem_u32(base + tile * 16384 +
                                        SMEM_SWIZZLE_128B(row * 128 + c16 * 16));
                CP_ASYNC16(dst, src);
            }
        }
        CP_COMMIT();
    };

    float acc[2][8][4];
    #pragma unroll
    for (int i = 0; i < 2; i++)
        #pragma unroll
        for (int j = 0; j < 8; j++)
            #pragma unroll
            for (int q = 0; q < 4; q++) acc[i][j][q] = 0.0f;

    stage(0, 0);
    stage(1, 1);

    for (int c = 0; c < 32; c++) {
        CP_WAIT1();
        __syncthreads();
        const uint32_t base = smem_u32(sm + (c & 1) * 65536);
        const uint32_t a0b = base, a1b = base + 16384;
        const uint32_t b0b = base + 32768, b1b = base + 49152;

        #pragma unroll
        for (int kk = 0; kk < 4; kk++) {
            uint32_t a0f[2][4], a1f[2][4];
            #pragma unroll
            for (int mt = 0; mt < 2; mt++) {
                int row = wm + mt * 16 + (lane & 15);
                uint32_t off = SMEM_SWIZZLE_128B(row * 128 + kk * 32 + (lane >> 4) * 16);
                LDMATRIX_X4(a0f[mt], a0b + off);
                LDMATRIX_X4(a1f[mt], a1b + off);
            }
            #pragma unroll
            for (int p = 0; p < 4; p++) {
                int nrow = wn + p * 16 + (lane & 15);
                uint32_t boff = SMEM_SWIZZLE_128B(nrow * 128 + kk * 32 + (lane >> 4) * 16);
                uint32_t f0[4], f1[4];
                LDMATRIX_X4(f0, b0b + boff);
                LDMATRIX_X4(f1, b1b + boff);
                #pragma unroll
                for (int mt = 0; mt < 2; mt++) {
                    MMA16816(acc[mt][2 * p],     a0f[mt], f0[0], f0[2]);
                    MMA16816(acc[mt][2 * p + 1], a0f[mt], f0[1], f0[3]);
                    MMA16816(acc[mt][2 * p],     a0f[mt], f1[0], f1[2]);
                    MMA16816(acc[mt][2 * p + 1], a0f[mt], f1[1], f1[3]);
                    MMA16816(acc[mt][2 * p],     a1f[mt], f0[0], f0[2]);
                    MMA16816(acc[mt][2 * p + 1], a1f[mt], f0[1], f0[3]);
                }
            }
        }
        __syncthreads();
        if (c + 2 < 32) stage(c & 1, c + 2);
    }

    #pragma unroll
    for (int mt = 0; mt < 2; mt++) {
        #pragma unroll
        for (int nt = 0; nt < 8; nt++) {
            int r = m0 + wm + mt * 16 + (lane >> 2);
            int col = n0 + wn + nt * 8 + (lane & 3) * 2;
            float2 v0 = make_float2(acc[mt][nt][0], acc[mt][nt][1]);
            float2 v1 = make_float2(acc[mt][nt][2], acc[mt][nt][3]);
            *reinterpret_cast<float2*>(C + (size_t)r * kD + col) = v0;
            *reinterpret_cast<float2*>(C + (size_t)(r + 8) * kD + col) = v1;
        }
    }
}

// ===========================================================================
// Persistent tensor-core recurrence. 128 CTAs x 256 thr. CTA owns 16 output
// cols, full K=2048; Wh fragments resident in registers. Per-warp cp.async
// chunk pipelining (4 commit groups) overlaps h staging with MMA.
// ===========================================================================
__device__ __forceinline__ void grid_barrier() {
    __syncthreads();
    if (threadIdx.x == 0) {
        __threadfence();
        unsigned gen = *((volatile unsigned*)&g_sense);
        if (atomicAdd(&g_count, 1) == gridDim.x - 1) {
            *((volatile unsigned*)&g_count) = 0;
            __threadfence();
            atomicAdd(&g_sense, 1);
        } else {
            while (*((volatile unsigned*)&g_sense) == gen) { }
        }
        __threadfence();
    }
    __syncthreads();
}

__global__ __launch_bounds__(256, 1) void rnn_scan_mma_kernel(
    const __nv_bfloat16* __restrict__ WhT0,
    const __nv_bfloat16* __restrict__ WhT1,
    float* __restrict__ hfinal_out)
{
    // dyn smem: [0,64K) h-hi chunks [32][16][64]; [64K,128K) h-lo; [128K,+8K) partials
    extern __shared__ char dsm_raw[];
    const uint32_t raw = smem_u32(dsm_raw);
    const uint32_t base = (raw + 1023u) & ~1023u;
    char* dsm = dsm_raw + (base - raw);
    float* part = reinterpret_cast<float*>(dsm + 131072);

    const int tid = threadIdx.x;
    const int wid = tid >> 5;
    const int lane = tid & 31;
    const int n0 = blockIdx.x * 16;

    // ---- init: stage Wh^T slice [n0:n0+16][0:2048] hi/lo, extract B frags ----
    {
        const __nv_bfloat16* s0 = WhT0 + (size_t)n0 * kD;
        const __nv_bfloat16* s1 = WhT1 + (size_t)n0 * kD;
        for (int i = tid; i < 4096; i += 256) {
            int row = i >> 8, u = i & 255, ch = u >> 3, c8 = u & 7;
            size_t so = (size_t)row * kD + ch * 64 + c8 * 8;
            uint32_t doff = ch * 2048 + SMEM_SWIZZLE_128B(row * 128 + c8 * 16);
            CP_ASYNC16(base + doff, s0 + so);
            CP_ASYNC16(base + 65536 + doff, s1 + so);
        }
        CP_COMMIT();
        CP_WAIT0();
        __syncthreads();
    }

    uint32_t bh[16][4], bl[16][4];       // 128 regs of resident Wh fragments
    #pragma unroll
    for (int s = 0; s < 16; s++) {
        const int ch = wid * 4 + (s >> 2), kk = s & 3;
        const uint32_t off = ch * 2048 +
            SMEM_SWIZZLE_128B((lane & 15) * 128 + kk * 32 + (lane >> 4) * 16);
        LDMATRIX_X4(bh[s], base + off);
        LDMATRIX_X4(bl[s], base + 65536 + off);
    }
    __syncthreads();   // Wh smem region now reused for h staging

    const int r0 = lane >> 2;
    const int cb = (lane & 3) * 2;
    const int rrow = tid >> 4;            // reduce-phase mapping
    const int rcol = tid & 15;

    // lane-fixed staging geometry (each warp stages only its own 4 chunks)
    const int ld_row_a = lane >> 2;            // rows 0..7   (j=0,1 pair)
    const int ld_row_b = 8 + (lane >> 2);      // rows 8..15
    const int ld_c8a = (lane & 3) * 2;         // c8 0,2,4,6
    const int ld_c8b = ld_c8a + 1;

    for (int t = 0; t < kT; t++) {
        const __nv_bfloat16* h0p = g_Hs0 + (size_t)t * kBD;
        const __nv_bfloat16* h1p = g_Hs1 + (size_t)t * kBD;

        // issue 4 pipelined chunk-pair groups (hi+lo), 8 cp.async/lane each
        #pragma unroll
        for (int g = 0; g < 4; g++) {
            const int ch = wid * 4 + g;
            const int rows[2] = {ld_row_a, ld_row_b};
            const int cs[2] = {ld_c8a, ld_c8b};
            #pragma unroll
            for (int ri = 0; ri < 2; ri++) {
                #pragma unroll
                for (int ci = 0; ci < 2; ci++) {
                    const int row = rows[ri], c8 = cs[ci];
                    size_t so = (size_t)row * kD + ch * 64 + c8 * 8;
                    uint32_t doff = ch * 2048 + SMEM_SWIZZLE_128B(row * 128 + c8 * 16);
                    CP_ASYNC16(base + doff, h0p + so);
                    CP_ASYNC16(base + 65536 + doff, h1p + so);
                }
            }
            CP_COMMIT();
        }

        // prefetch Xp bias for this thread's reduce element
        const float xp = __ldg(g_Xp + (size_t)t * kBD + (size_t)rrow * kD + n0 + rcol);

        float acc[2][4];
        #pragma unroll
        for (int p = 0; p < 2; p++)
            #pragma unroll
            for (int q = 0; q < 4; q++) acc[p][q] = 0.0f;

        // consume chunk g as soon as its group lands; later groups keep loading
        #define SCAN_GROUP(gc)                                                   \
        {                                                                        \
            asm volatile("cp.async.wait_group %0;" :: "n"(3 - (gc)) : "memory"); \
            __syncwarp();                                                        \
            const int ch = wid * 4 + (gc);                                       \
            _Pragma("unroll")                                                    \
            for (int kk = 0; kk < 4; kk++) {                                     \
                const int s = (gc) * 4 + kk;                                     \
                const uint32_t off = ch * 2048 +                                 \
                    SMEM_SWIZZLE_128B((lane & 15) * 128 + kk * 32 +              \
                                      (lane >> 4) * 16);                         \
                uint32_t a0[4], a1[4];                                           \
                LDMATRIX_X4(a0, base + off);                                     \
                LDMATRIX_X4(a1, base + 65536 + off);                             \
                MMA16816(acc[0], a0, bh[s][0], bh[s][2]);                        \
                MMA16816(acc[1], a0, bh[s][1], bh[s][3]);                        \
                MMA16816(acc[0], a0, bl[s][0], bl[s][2]);                        \
                MMA16816(acc[1], a0, bl[s][1], bl[s][3]);                        \
                MMA16816(acc[0], a1, bh[s][0], bh[s][2]);                        \
                MMA16816(acc[1], a1, bh[s][1], bh[s][3]);                        \
            }                                                                    \
        }
        SCAN_GROUP(0)
        SCAN_GROUP(1)
        SCAN_GROUP(2)
        SCAN_GROUP(3)
        #undef SCAN_GROUP

        // per-warp partials -> smem
        #pragma unroll
        for (int p = 0; p < 2; p++) {
            *reinterpret_cast<float2*>(&part[wid * 256 + r0 * 16 + p * 8 + cb]) =
                make_float2(acc[p][0], acc[p][1]);
            *reinterpret_cast<float2*>(&part[wid * 256 + (r0 + 8) * 16 + p * 8 + cb]) =
                make_float2(acc[p][2], acc[p][3]);
        }
        __syncthreads();

        // reduce 8 warps + Xp, tanh, split, store
        {
            float s = xp;
            #pragma unroll
            for (int w = 0; w < 8; w++) s += part[w * 256 + tid];
            float h = tanhf(s);
            __nv_bfloat16 hb = __float2bfloat16_rn(h);
            size_t go = (size_t)(t + 1) * kBD + (size_t)rrow * kD + n0 + rcol;
            g_Hs0[go] = hb;
            g_Hs1[go] = __float2bfloat16_rn(h - __bfloat162float(hb));
            if (t == kT - 1)
                hfinal_out[(size_t)rrow * kD + n0 + rcol] = h;
        }

        if (t + 1 < kT) grid_barrier();
    }
}

// ===========================================================================
// Launch
// ===========================================================================
extern "C" void kernel_launch(void* const* d_in, const int* in_sizes, int n_in,
                              void* d_out, int out_size)
{
    const float* h0 = (const float*)d_in[0];
    const float* x  = (const float*)d_in[1];
    const float* Wx = (const float*)d_in[2];
    const float* Wh = (const float*)d_in[3];
    const float* Wo = (const float*)d_in[4];

    float* out  = (float*)d_out;
    float* hfin = out;                 // [B, D]
    float* ys   = out + kBD;           // [T, B, D]

    float* Xp;
    __nv_bfloat16 *Hs0, *Hs1, *Xs0, *Xs1, *WxT0, *WxT1, *WoT0, *WoT1, *WhT0, *WhT1;
    cudaGetSymbolAddress((void**)&Xp,   g_Xp);
    cudaGetSymbolAddress((void**)&Hs0,  g_Hs0);
    cudaGetSymbolAddress((void**)&Hs1,  g_Hs1);
    cudaGetSymbolAddress((void**)&Xs0,  g_Xs0);
    cudaGetSymbolAddress((void**)&Xs1,  g_Xs1);
    cudaGetSymbolAddress((void**)&WxT0, g_WxT0);
    cudaGetSymbolAddress((void**)&WxT1, g_WxT1);
    cudaGetSymbolAddress((void**)&WoT0, g_WoT0);
    cudaGetSymbolAddress((void**)&WoT1, g_WoT1);
    cudaGetSymbolAddress((void**)&WhT0, g_WhT0);
    cudaGetSymbolAddress((void**)&WhT1, g_WhT1);

    const int gemm_smem = 2 * 65536;                 // 128 KB
    const int scan_smem = 131072 + 8192 + 1024;      // 140 KB
    cudaFuncSetAttribute(gemm_bf16_kernel,
                         cudaFuncAttributeMaxDynamicSharedMemorySize, gemm_smem);
    cudaFuncSetAttribute(rnn_scan_mma_kernel,
                         cudaFuncAttributeMaxDynamicSharedMemorySize, scan_smem);

    dim3 prep_grid(kD / 32, kD / 32), prep_blk(32, 32);
    prep_wT_kernel<<<prep_grid, prep_blk>>>(Wx, WxT0, WxT1);
    prep_wT_kernel<<<prep_grid, prep_blk>>>(Wo, WoT0, WoT1);
    prep_wT_kernel<<<prep_grid, prep_blk>>>(Wh, WhT0, WhT1);

    const int n4x = kM * kD / 4;
    split_bf16_kernel<<<(n4x + 255) / 256, 256>>>(x, Xs0, Xs1, n4x);
    const int n4h = kBD / 4;
    split_bf16_kernel<<<(n4h + 255) / 256, 256>>>(h0, Hs0, Hs1, n4h);  // slot 0

    dim3 gemm_grid(kD / 128, kM / 128);   // (16, 64)

    // 1) Xp = X @ Wx  (HMMA bf16x3)
    gemm_bf16_kernel<<<gemm_grid, 256, gemm_smem>>>(Xs0, Xs1, WxT0, WxT1, Xp);

    // 2) sequential scan: tensor-core recurrence, writes Hs slots 1..T
    rnn_scan_mma_kernel<<<128, 256, scan_smem>>>(WhT0, WhT1, hfin);

    // 3) ys = H @ Wo  (HMMA bf16x3; A = Hs slots 1..T)
    gemm_bf16_kernel<<<gemm_grid, 256, gemm_smem>>>(Hs0 + kBD, Hs1 + kBD,
                                                    WoT0, WoT1, ys);
}